// round 12
// baseline (speedup 1.0000x reference)
#include <cuda_runtime.h>
#include <float.h>
#include <math.h>

#define N_PROT 50000
#define N_SUB  2000
#define D      256     // D_PROT == D_SUB
#define DP     128     // D_PROJ
#define KERN   16
#define N_INT  64
#define NW     (N_PROT - KERN + 1)   // 49985

#define NBLK    444       // 3 * 148 SMs — all resident (launch_bounds(256,3))
#define NB_WIN  196       // 196*256 = 50176 >= NW
#define N_RPART 8
#define PCHUNK  3125      // prot chunks of 16 rows (2 rows/warp)

// -------- device scratch (no allocations allowed) --------
__device__ float d_g[N_PROT];
__device__ float d_s[N_PROT];
__device__ float d_v[D];          // Wp @ w1
__device__ float d_u[D];          // Wp @ ones
__device__ float d_react_part[N_RPART * DP];
__device__ float d_blkVal[NB_WIN];
__device__ int   d_blkIdx[NB_WIN];
__device__ int   d_count;         // finalize ticket; reset by finalize
__device__ int   d_vu_done;       // v/u flag;        reset by finalize
__device__ int   d_bar;           // barrier;         reset by finalize

__device__ __forceinline__ float dot4(float4 a, float4 b) {
    return a.x*b.x + a.y*b.y + a.z*b.z + a.w*b.w;
}

__global__ void __launch_bounds__(256, 3)
mega(const float* __restrict__ prot,
     const float* __restrict__ subn,
     const int*   __restrict__ idx,
     const float* __restrict__ Wp,
     const float* __restrict__ bp,
     const float* __restrict__ Ws,
     const float* __restrict__ bs,
     const float* __restrict__ wa,
     const float* __restrict__ sub_out,
     const float* __restrict__ prot_out,
     float* __restrict__ out)
{
    __shared__ float sv[D];           // staged v
    __shared__ float su[D];           // staged u
    __shared__ float sacc[8][32];
    __shared__ float ssumL[32];
    __shared__ float sg[256 + KERN];
    __shared__ float ss[256 + KERN];
    __shared__ float bval[256];
    __shared__ int   bidx[256];
    __shared__ int   s_last, s_top;
    __shared__ float attn[KERN];
    __shared__ float wrow[D];
    __shared__ float ts[DP];
    __shared__ float tpart[DP];
    __shared__ float dprot[D];
    __shared__ float dsub[D];

    int b    = blockIdx.x;
    int t    = threadIdx.x;
    int warp = t >> 5;
    int lane = t & 31;

    // ---------------- producer prologue ----------------
    if (b < 32) {
        // v/u: one warp per Wp row, single coalesced float4 load
        int row = b * 8 + warp;
        float4 w = ((const float4*)(Wp + (size_t)row * DP))[lane];
        float4 a = ((const float4*)wa)[lane];
        float vv = dot4(w, a);
        float uu = w.x + w.y + w.z + w.w;
        #pragma unroll
        for (int o = 16; o > 0; o >>= 1) {
            vv += __shfl_xor_sync(0xffffffffu, vv, o);
            uu += __shfl_xor_sync(0xffffffffu, uu, o);
        }
        if (lane == 0) { d_v[row] = vv; d_u[row] = uu; }
        __syncthreads();
        if (t == 0) { __threadfence(); atomicAdd(&d_vu_done, 1); }
    } else if (b < 32 + N_RPART) {
        // reaction partial over j-slice [j0, j0+32)
        int r  = b - 32;
        int j0 = r * 32;
        int col  = t & 31;
        int row8 = t >> 5;
        float acc = 0.f;
        #pragma unroll
        for (int p = 0; p < 8; p++)
            acc += subn[(size_t)idx[p * 8 + row8] * D + j0 + col];
        sacc[row8][col] = acc;
        __syncthreads();
        if (t < 32) {
            float s = 0.f;
            #pragma unroll
            for (int r8 = 0; r8 < 8; r8++) s += sacc[r8][t];
            ssumL[t] = s;
        }
        __syncthreads();
        if (t < DP) {
            float p = 0.f;
            #pragma unroll
            for (int j = 0; j < 32; j++)
                p += ssumL[j] * Ws[(j0 + j) * DP + t];
            d_react_part[r * DP + t] = p;
        }
    } else if (b == NBLK - 1) {
        // idx tail (b=443 is odd -> not a window block)
        if (t < N_INT)
            out[(size_t)(N_PROT + N_SUB) * D + t] = (float)idx[t];
    }

    // ---------------- stage v/u to shared (all blocks) ----------------
    if (t == 0)
        while (((volatile int*)&d_vu_done)[0] < 32) __nanosleep(32);
    __syncthreads();
    sv[t] = d_v[t];
    su[t] = d_u[t];
    __syncthreads();

    // ---------------- phase A: g/s matvec (read-only streaming, pipelined) ----------------
    {
        int chunk = b;
        if (chunk < PCHUNK) {
            const float4* sv4 = (const float4*)sv;
            const float4* su4 = (const float4*)su;
            float4 va = sv4[lane], vc = sv4[lane + 32];
            float4 ua = su4[lane], uc = su4[lane + 32];

            const float4* src = (const float4*)(prot + (size_t)(chunk * 16 + warp * 2) * D);
            float4 a0 = src[lane];
            float4 c0 = src[lane + 32];
            float4 a1 = src[64 + lane];
            float4 c1 = src[64 + lane + 32];

            while (true) {
                int nxt = chunk + NBLK;
                bool hn = nxt < PCHUNK;
                float4 n0, n1, n2, n3;
                if (hn) {
                    const float4* nsrc = (const float4*)(prot + (size_t)(nxt * 16 + warp * 2) * D);
                    n0 = nsrc[lane];
                    n1 = nsrc[lane + 32];
                    n2 = nsrc[64 + lane];
                    n3 = nsrc[64 + lane + 32];
                }

                int row = chunk * 16 + warp * 2;
                float g0 = dot4(a0, va) + dot4(c0, vc);
                float s0 = dot4(a0, ua) + dot4(c0, uc);
                float g1 = dot4(a1, va) + dot4(c1, vc);
                float s1 = dot4(a1, ua) + dot4(c1, uc);
                #pragma unroll
                for (int o = 16; o > 0; o >>= 1) {
                    g0 += __shfl_down_sync(0xffffffffu, g0, o);
                    s0 += __shfl_down_sync(0xffffffffu, s0, o);
                    g1 += __shfl_down_sync(0xffffffffu, g1, o);
                    s1 += __shfl_down_sync(0xffffffffu, s1, o);
                }
                if (lane == 0) {
                    d_g[row]     = g0;  d_s[row]     = s0;
                    d_g[row + 1] = g1;  d_s[row + 1] = s1;
                }

                if (!hn) break;
                a0 = n0; c0 = n1; a1 = n2; c1 = n3;
                chunk = nxt;
            }
        }
    }

    // ---------------- grid barrier (arrive; non-phase-B exit) ----------------
    __syncthreads();
    if (t == 0) {
        __threadfence();
        atomicAdd(&d_bar, 1);
    }
    bool isWin = ((b & 1) == 0) && ((b >> 1) < NB_WIN);   // 196 even blocks
    if (!isWin) return;
    int wb = b >> 1;                    // window-block id, 0..195
    if (t == 0) {
        while (((volatile int*)&d_bar)[0] < NBLK) __nanosleep(64);
        __threadfence();
    }
    __syncthreads();

    // ---------------- phase B: windows + block argmax ----------------
    {
        int base = wb * 256;
        for (int i = t; i < 256 + KERN - 1; i += 256) {
            int gi = base + i;
            sg[i] = (gi < N_PROT) ? d_g[gi] : -FLT_MAX;
            ss[i] = (gi < N_PROT) ? d_s[gi] : 0.f;
        }
        __syncthreads();

        int   w = base + t;
        float A = -FLT_MAX;
        if (w < NW) {
            float m = sg[t];
            #pragma unroll
            for (int k = 1; k < KERN; k++) m = fmaxf(m, sg[t + k]);
            float wsum = 0.f, asum = 0.f;
            #pragma unroll
            for (int k = 0; k < KERN; k++) {
                float e = expf(sg[t + k] - m);
                wsum += e;
                asum += e * ss[t + k];
            }
            A = asum / wsum;
        }
        bval[t] = A;
        bidx[t] = w;
        __syncthreads();

        for (int off = 128; off > 0; off >>= 1) {
            if (t < off) {
                float ov = bval[t + off];
                int   oi = bidx[t + off];
                if (ov > bval[t] || (ov == bval[t] && oi < bidx[t])) {
                    bval[t] = ov;
                    bidx[t] = oi;
                }
            }
            __syncthreads();
        }
        if (t == 0) {
            d_blkVal[wb] = bval[0];
            d_blkIdx[wb] = bidx[0];
        }
    }

    // ---------------- ticket among window blocks: last finalizes ----------------
    __syncthreads();
    if (t == 0) {
        __threadfence();
        s_last = (atomicAdd(&d_count, 1) == NB_WIN - 1);
    }
    __syncthreads();
    if (!s_last) return;

    // reduce 196 candidates -> top
    if (t < NB_WIN) { bval[t] = d_blkVal[t]; bidx[t] = d_blkIdx[t]; }
    else            { bval[t] = -FLT_MAX;    bidx[t] = 0x7fffffff; }
    __syncthreads();
    for (int off = 128; off > 0; off >>= 1) {
        if (t < off) {
            float ov = bval[t + off];
            int   oi = bidx[t + off];
            if (ov > bval[t] || (ov == bval[t] && oi < bidx[t])) {
                bval[t] = ov;
                bidx[t] = oi;
            }
        }
        __syncthreads();
    }
    if (t == 0) {
        s_top = bidx[0];
        d_count = 0; d_vu_done = 0; d_bar = 0;   // reset for graph replay
    }
    __syncthreads();
    int top = s_top;

    // attn (one warp)
    if (t < 32) {
        float gk = (t < KERN) ? d_g[top + t] : -FLT_MAX;
        float m = gk;
        #pragma unroll
        for (int o = 16; o > 0; o >>= 1)
            m = fmaxf(m, __shfl_xor_sync(0xffffffffu, m, o));
        float e = (t < KERN) ? expf(gk - m) : 0.f;
        float sum = e;
        #pragma unroll
        for (int o = 16; o > 0; o >>= 1)
            sum += __shfl_xor_sync(0xffffffffu, sum, o);
        if (t < KERN) attn[t] = e / sum;
    }
    __syncthreads();

    // weighted prot row
    {
        float acc = 0.f;
        #pragma unroll
        for (int k = 0; k < KERN; k++)
            acc += attn[k] * prot[(size_t)(top + k) * D + t];
        wrow[t] = acc;
    }
    __syncthreads();

    // top_score[d] = sum_r react_part[r][d] + 64*bs[d] + bp[d] + wrow @ Wp[:,d]
    {
        int c    = t & (DP - 1);
        int half = t >> 7;
        int j0   = half * (D / 2);
        float acc = 0.f;
        #pragma unroll 32
        for (int j = 0; j < D / 2; j++)
            acc += wrow[j0 + j] * Wp[(j0 + j) * DP + c];
        if (half) tpart[c] = acc;
        __syncthreads();
        if (!half) {
            float rp = 0.f;
            #pragma unroll
            for (int r = 0; r < N_RPART; r++) rp += d_react_part[r * DP + c];
            ts[c] = acc + tpart[c] + rp + (float)N_INT * bs[c] + bp[c];
        }
    }
    __syncthreads();

    // deltas
    {
        float dp_ = 0.f, ds_ = 0.f;
        #pragma unroll 32
        for (int d = 0; d < DP; d++) {
            float s = ts[d];
            dp_ += s * prot_out[d * D + t];
            ds_ += s * sub_out[d * D + t];
        }
        dprot[t] = dp_;
        dsub[t]  = ds_;
    }
    __syncthreads();

    // patch 16 prot rows (out holds the memcpy'd copy; same-stream order)
    #pragma unroll
    for (int k = 0; k < KERN; k++)
        out[(size_t)(top + k) * D + t] += dprot[t];

    // patch 64 sub rows (set semantics; duplicates identical)
    #pragma unroll 4
    for (int m = 0; m < N_INT; m++) {
        int r = idx[m];
        out[(size_t)(N_PROT + r) * D + t] = subn[(size_t)r * D + t] + dsub[t];
    }
}

// ============================================================
extern "C" void kernel_launch(void* const* d_in, const int* in_sizes, int n_in,
                              void* d_out, int out_size)
{
    const float* prot_node = (const float*)d_in[0];
    const float* sub_node  = (const float*)d_in[1];
    const int*   int_index = (const int*)  d_in[2];
    const float* Wp        = (const float*)d_in[3];
    const float* bp        = (const float*)d_in[4];
    const float* Ws        = (const float*)d_in[5];
    const float* bs        = (const float*)d_in[6];
    const float* wa        = (const float*)d_in[7];
    const float* sub_out   = (const float*)d_in[9];
    const float* prot_out  = (const float*)d_in[10];
    float*       out       = (float*)d_out;

    // Bulk copy via copy engine (graph memcpy nodes; SM-free)
    cudaMemcpyAsync(out, prot_node,
                    (size_t)N_PROT * D * sizeof(float),
                    cudaMemcpyDeviceToDevice, 0);
    cudaMemcpyAsync(out + (size_t)N_PROT * D, sub_node,
                    (size_t)N_SUB * D * sizeof(float),
                    cudaMemcpyDeviceToDevice, 0);

    mega<<<NBLK, 256>>>(prot_node, sub_node, int_index, Wp, bp, Ws, bs, wa,
                        sub_out, prot_out, out);
}

// round 13
// speedup vs baseline: 1.0023x; 1.0023x over previous
#include <cuda_runtime.h>
#include <float.h>
#include <math.h>
#include <stdint.h>

#define N_PROT 50000
#define N_SUB  2000
#define D      256     // D_PROT == D_SUB
#define DP     128     // D_PROJ
#define KERN   16
#define N_INT  64
#define NW     (N_PROT - KERN + 1)   // 49985

#define NBLK    296       // 2 * 148 SMs — all resident (launch_bounds(256,2))
#define NB_WIN  196
#define N_RPART 8

#define TK_PROT 3125      // 16-row chunks of prot (16*256 floats = 16KB)
#define TK_SUB  125       // 16-row chunks of sub
#define NTOT    (TK_PROT + TK_SUB)
#define CHUNK_FLOATS 4096
#define CHUNK_BYTES  16384

// -------- device scratch (no allocations allowed) --------
__device__ float d_g[N_PROT];
__device__ float d_s[N_PROT];
__device__ float d_v[D];          // Wp @ w1
__device__ float d_u[D];          // Wp @ ones
__device__ float d_react_part[N_RPART * DP];
__device__ float d_blkVal[NB_WIN];
__device__ int   d_blkIdx[NB_WIN];
__device__ int   d_count;         // finalize ticket; reset by finalize
__device__ int   d_vu_done;       // v/u flag;        reset by finalize
__device__ int   d_bar;           // barrier;         reset by finalize

__device__ __forceinline__ float dot4(float4 a, float4 b) {
    return a.x*b.x + a.y*b.y + a.z*b.z + a.w*b.w;
}

__device__ __forceinline__ uint32_t smem_u32(const void* p) {
    uint32_t a;
    asm("{ .reg .u64 t; cvta.to.shared.u64 t, %1; cvt.u32.u64 %0, t; }" : "=r"(a) : "l"(p));
    return a;
}
__device__ __forceinline__ void mbar_init(uint32_t a, uint32_t c) {
    asm volatile("mbarrier.init.shared.b64 [%0], %1;" :: "r"(a), "r"(c) : "memory");
}
__device__ __forceinline__ void mbar_expect_tx(uint32_t a, uint32_t bytes) {
    asm volatile("mbarrier.arrive.expect_tx.shared.b64 _, [%0], %1;" :: "r"(a), "r"(bytes) : "memory");
}
__device__ __forceinline__ void mbar_wait(uint32_t a, uint32_t parity) {
    asm volatile(
        "{\n\t.reg .pred P;\n\t"
        "WL_%=:\n\t"
        "mbarrier.try_wait.parity.acquire.cta.shared::cta.b64 P, [%0], %1, 0x989680;\n\t"
        "@P bra.uni WD_%=;\n\t"
        "bra.uni WL_%=;\n\t"
        "WD_%=:\n\t}"
        :: "r"(a), "r"(parity) : "memory");
}
__device__ __forceinline__ void bulk_g2s(uint32_t sdst, const void* gsrc, uint32_t bytes, uint32_t mbar) {
    asm volatile("cp.async.bulk.shared::cta.global.mbarrier::complete_tx::bytes [%0], [%1], %2, [%3];"
        :: "r"(sdst), "l"(gsrc), "r"(bytes), "r"(mbar) : "memory");
}
__device__ __forceinline__ void bulk_s2g(void* gdst, uint32_t ssrc, uint32_t bytes) {
    asm volatile("cp.async.bulk.global.shared::cta.bulk_group [%0], [%1], %2;"
        :: "l"(gdst), "r"(ssrc), "r"(bytes) : "memory");
}
#define BULK_COMMIT() asm volatile("cp.async.bulk.commit_group;" ::: "memory")
#define BULK_WAIT(n)  asm volatile("cp.async.bulk.wait_group %0;" :: "n"(n) : "memory")

__global__ void __launch_bounds__(256, 2)
mega(const float* __restrict__ prot,
     const float* __restrict__ subn,
     const int*   __restrict__ idx,
     const float* __restrict__ Wp,
     const float* __restrict__ bp,
     const float* __restrict__ Ws,
     const float* __restrict__ bs,
     const float* __restrict__ wa,
     const float* __restrict__ sub_out,
     const float* __restrict__ prot_out,
     float* __restrict__ out)
{
    extern __shared__ float dynbuf[];          // 4 x 4096 floats (64KB ring)
    __shared__ uint64_t mbar[4];
    __shared__ float sv[D];
    __shared__ float su[D];
    __shared__ float sacc[8][32];
    __shared__ float ssumL[32];
    __shared__ float sg[256 + KERN];
    __shared__ float ss[256 + KERN];
    __shared__ float bval[256];
    __shared__ int   bidx[256];
    __shared__ int   s_last, s_top;
    __shared__ float attn[KERN];
    __shared__ float wrow[D];
    __shared__ float ts[DP];
    __shared__ float tpart[DP];
    __shared__ float dprot[D];
    __shared__ float dsub[D];

    int b    = blockIdx.x;
    int t    = threadIdx.x;
    int warp = t >> 5;
    int lane = t & 31;

    // ---------------- mbar init + prologue bulk loads ----------------
    if (t == 0) {
        #pragma unroll
        for (int j = 0; j < 4; j++) mbar_init(smem_u32(&mbar[j]), 1);
        asm volatile("fence.proxy.async.shared::cta;" ::: "memory");
        #pragma unroll
        for (int k0 = 0; k0 < 2; k0++) {
            int c = b + k0 * NBLK;
            if (c < NTOT) {
                const float* src = (c < TK_PROT)
                    ? prot + (size_t)c * CHUNK_FLOATS
                    : subn + (size_t)(c - TK_PROT) * CHUNK_FLOATS;
                mbar_expect_tx(smem_u32(&mbar[k0]), CHUNK_BYTES);
                bulk_g2s(smem_u32(dynbuf) + k0 * CHUNK_BYTES, src, CHUNK_BYTES,
                         smem_u32(&mbar[k0]));
            }
        }
    }
    __syncthreads();   // mbar init visible to all waiters

    // ---------------- producer roles ----------------
    if (b < 32) {
        int row = b * 8 + warp;
        float4 w = ((const float4*)(Wp + (size_t)row * DP))[lane];
        float4 a = ((const float4*)wa)[lane];
        float vv = dot4(w, a);
        float uu = w.x + w.y + w.z + w.w;
        #pragma unroll
        for (int o = 16; o > 0; o >>= 1) {
            vv += __shfl_xor_sync(0xffffffffu, vv, o);
            uu += __shfl_xor_sync(0xffffffffu, uu, o);
        }
        if (lane == 0) { d_v[row] = vv; d_u[row] = uu; }
        __syncthreads();
        if (t == 0) { __threadfence(); atomicAdd(&d_vu_done, 1); }
    } else if (b < 32 + N_RPART) {
        int r  = b - 32;
        int j0 = r * 32;
        int col  = t & 31;
        int row8 = t >> 5;
        float acc = 0.f;
        #pragma unroll
        for (int p = 0; p < 8; p++)
            acc += subn[(size_t)idx[p * 8 + row8] * D + j0 + col];
        sacc[row8][col] = acc;
        __syncthreads();
        if (t < 32) {
            float s = 0.f;
            #pragma unroll
            for (int r8 = 0; r8 < 8; r8++) s += sacc[r8][t];
            ssumL[t] = s;
        }
        __syncthreads();
        if (t < DP) {
            float p = 0.f;
            #pragma unroll
            for (int j = 0; j < 32; j++)
                p += ssumL[j] * Ws[(j0 + j) * DP + t];
            d_react_part[r * DP + t] = p;
        }
    } else if (b == NBLK - 1) {
        if (t < N_INT)
            out[(size_t)(N_PROT + N_SUB) * D + t] = (float)idx[t];
    }

    // ---------------- v/u gate + stage to shared ----------------
    if (t == 0)
        while (((volatile int*)&d_vu_done)[0] < 32) __nanosleep(32);
    __syncthreads();
    sv[t] = d_v[t];
    su[t] = d_u[t];
    __syncthreads();

    // ---------------- phase A: bulk-ring copy + g/s from smem ----------------
    {
        const float4* sv4 = (const float4*)sv;
        const float4* su4 = (const float4*)su;
        float4 va = sv4[lane], vc = sv4[lane + 32];
        float4 ua = su4[lane], uc = su4[lane + 32];
        unsigned ph = 0;   // parity bit per ring slot

        for (int k = 0; ; k++) {
            int c = b + k * NBLK;
            if (c >= NTOT) break;
            int j = k & 3;

            // issue load for k+2 (ring slot stored at iter k-2; wait_group(1) drains it)
            if (t == 0) {
                int c2 = b + (k + 2) * NBLK;
                if (c2 < NTOT) {
                    int j2 = (k + 2) & 3;
                    BULK_WAIT(1);
                    const float* src = (c2 < TK_PROT)
                        ? prot + (size_t)c2 * CHUNK_FLOATS
                        : subn + (size_t)(c2 - TK_PROT) * CHUNK_FLOATS;
                    mbar_expect_tx(smem_u32(&mbar[j2]), CHUNK_BYTES);
                    bulk_g2s(smem_u32(dynbuf) + j2 * CHUNK_BYTES, src, CHUNK_BYTES,
                             smem_u32(&mbar[j2]));
                }
            }

            // wait for this chunk's data
            mbar_wait(smem_u32(&mbar[j]), (ph >> j) & 1u);
            ph ^= (1u << j);

            // compute g/s for prot chunks (warp = 2 rows)
            if (c < TK_PROT) {
                const float4* buf = (const float4*)(dynbuf + j * CHUNK_FLOATS);
                int rl = warp * 2;                   // local row
                float4 a0 = buf[rl * 64 + lane];
                float4 c0 = buf[rl * 64 + lane + 32];
                float4 a1 = buf[rl * 64 + 64 + lane];
                float4 c1 = buf[rl * 64 + 64 + lane + 32];

                float g0 = dot4(a0, va) + dot4(c0, vc);
                float s0 = dot4(a0, ua) + dot4(c0, uc);
                float g1 = dot4(a1, va) + dot4(c1, vc);
                float s1 = dot4(a1, ua) + dot4(c1, uc);

                // stages o=16,8 on all four (each lane ends with its lane%8 subgroup sums)
                #pragma unroll
                for (int o = 16; o >= 8; o >>= 1) {
                    g0 += __shfl_xor_sync(0xffffffffu, g0, o);
                    s0 += __shfl_xor_sync(0xffffffffu, s0, o);
                    g1 += __shfl_xor_sync(0xffffffffu, g1, o);
                    s1 += __shfl_xor_sync(0xffffffffu, s1, o);
                }
                // select per 8-lane group, finish with 3 shared stages
                float v = (lane < 8) ? g0 : (lane < 16) ? s0 : (lane < 24) ? g1 : s1;
                v += __shfl_xor_sync(0xffffffffu, v, 4);
                v += __shfl_xor_sync(0xffffffffu, v, 2);
                v += __shfl_xor_sync(0xffffffffu, v, 1);

                int row = c * 16 + rl;
                if ((lane & 7) == 0) {
                    if (lane == 0)       d_g[row]     = v;
                    else if (lane == 8)  d_s[row]     = v;
                    else if (lane == 16) d_g[row + 1] = v;
                    else                 d_s[row + 1] = v;
                }
            }

            __syncthreads();   // all reads of buf done before store reuses it

            if (t == 0) {
                float* dst = (c < TK_PROT)
                    ? out + (size_t)c * CHUNK_FLOATS
                    : out + (size_t)N_PROT * D + (size_t)(c - TK_PROT) * CHUNK_FLOATS;
                bulk_s2g(dst, smem_u32(dynbuf) + j * CHUNK_BYTES, CHUNK_BYTES);
                BULK_COMMIT();
            }
        }
    }

    // drain all bulk stores before signaling (finalize patches `out`)
    if (t == 0) BULK_WAIT(0);
    __syncthreads();

    // ---------------- grid barrier (arrive; non-phase-B exit) ----------------
    if (t == 0) {
        __threadfence();
        atomicAdd(&d_bar, 1);
    }
    if (b >= NB_WIN) return;
    int wb = b;
    if (t == 0) {
        while (((volatile int*)&d_bar)[0] < NBLK) __nanosleep(64);
        __threadfence();
    }
    __syncthreads();

    // ---------------- phase B: windows + block argmax ----------------
    {
        int base = wb * 256;
        for (int i = t; i < 256 + KERN - 1; i += 256) {
            int gi = base + i;
            sg[i] = (gi < N_PROT) ? d_g[gi] : -FLT_MAX;
            ss[i] = (gi < N_PROT) ? d_s[gi] : 0.f;
        }
        __syncthreads();

        int   w = base + t;
        float A = -FLT_MAX;
        if (w < NW) {
            float m = sg[t];
            #pragma unroll
            for (int k = 1; k < KERN; k++) m = fmaxf(m, sg[t + k]);
            float wsum = 0.f, asum = 0.f;
            #pragma unroll
            for (int k = 0; k < KERN; k++) {
                float e = expf(sg[t + k] - m);
                wsum += e;
                asum += e * ss[t + k];
            }
            A = asum / wsum;
        }
        bval[t] = A;
        bidx[t] = w;
        __syncthreads();

        for (int off = 128; off > 0; off >>= 1) {
            if (t < off) {
                float ov = bval[t + off];
                int   oi = bidx[t + off];
                if (ov > bval[t] || (ov == bval[t] && oi < bidx[t])) {
                    bval[t] = ov;
                    bidx[t] = oi;
                }
            }
            __syncthreads();
        }
        if (t == 0) {
            d_blkVal[wb] = bval[0];
            d_blkIdx[wb] = bidx[0];
        }
    }

    // ---------------- ticket among window blocks: last finalizes ----------------
    __syncthreads();
    if (t == 0) {
        __threadfence();
        s_last = (atomicAdd(&d_count, 1) == NB_WIN - 1);
    }
    __syncthreads();
    if (!s_last) return;

    // reduce 196 candidates -> top
    if (t < NB_WIN) { bval[t] = d_blkVal[t]; bidx[t] = d_blkIdx[t]; }
    else            { bval[t] = -FLT_MAX;    bidx[t] = 0x7fffffff; }
    __syncthreads();
    for (int off = 128; off > 0; off >>= 1) {
        if (t < off) {
            float ov = bval[t + off];
            int   oi = bidx[t + off];
            if (ov > bval[t] || (ov == bval[t] && oi < bidx[t])) {
                bval[t] = ov;
                bidx[t] = oi;
            }
        }
        __syncthreads();
    }
    if (t == 0) {
        s_top = bidx[0];
        d_count = 0; d_vu_done = 0; d_bar = 0;   // reset for graph replay
    }
    __syncthreads();
    int top = s_top;

    // attn (one warp)
    if (t < 32) {
        float gk = (t < KERN) ? d_g[top + t] : -FLT_MAX;
        float m = gk;
        #pragma unroll
        for (int o = 16; o > 0; o >>= 1)
            m = fmaxf(m, __shfl_xor_sync(0xffffffffu, m, o));
        float e = (t < KERN) ? expf(gk - m) : 0.f;
        float sum = e;
        #pragma unroll
        for (int o = 16; o > 0; o >>= 1)
            sum += __shfl_xor_sync(0xffffffffu, sum, o);
        if (t < KERN) attn[t] = e / sum;
    }
    __syncthreads();

    // weighted prot row
    {
        float acc = 0.f;
        #pragma unroll
        for (int k = 0; k < KERN; k++)
            acc += attn[k] * prot[(size_t)(top + k) * D + t];
        wrow[t] = acc;
    }
    __syncthreads();

    // top_score[d] = sum_r react_part[r][d] + 64*bs[d] + bp[d] + wrow @ Wp[:,d]
    {
        int c    = t & (DP - 1);
        int half = t >> 7;
        int j0   = half * (D / 2);
        float acc = 0.f;
        #pragma unroll 32
        for (int j = 0; j < D / 2; j++)
            acc += wrow[j0 + j] * Wp[(j0 + j) * DP + c];
        if (half) tpart[c] = acc;
        __syncthreads();
        if (!half) {
            float rp = 0.f;
            #pragma unroll
            for (int r = 0; r < N_RPART; r++) rp += d_react_part[r * DP + c];
            ts[c] = acc + tpart[c] + rp + (float)N_INT * bs[c] + bp[c];
        }
    }
    __syncthreads();

    // deltas
    {
        float dp_ = 0.f, ds_ = 0.f;
        #pragma unroll 32
        for (int d = 0; d < DP; d++) {
            float s = ts[d];
            dp_ += s * prot_out[d * D + t];
            ds_ += s * sub_out[d * D + t];
        }
        dprot[t] = dp_;
        dsub[t]  = ds_;
    }
    __syncthreads();

    // patch 16 prot rows
    #pragma unroll
    for (int k = 0; k < KERN; k++)
        out[(size_t)(top + k) * D + t] += dprot[t];

    // patch 64 sub rows (set semantics; duplicates identical)
    #pragma unroll 4
    for (int m = 0; m < N_INT; m++) {
        int r = idx[m];
        out[(size_t)(N_PROT + r) * D + t] = subn[(size_t)r * D + t] + dsub[t];
    }
}

// ============================================================
extern "C" void kernel_launch(void* const* d_in, const int* in_sizes, int n_in,
                              void* d_out, int out_size)
{
    const float* prot_node = (const float*)d_in[0];
    const float* sub_node  = (const float*)d_in[1];
    const int*   int_index = (const int*)  d_in[2];
    const float* Wp        = (const float*)d_in[3];
    const float* bp        = (const float*)d_in[4];
    const float* Ws        = (const float*)d_in[5];
    const float* bs        = (const float*)d_in[6];
    const float* wa        = (const float*)d_in[7];
    const float* sub_out   = (const float*)d_in[9];
    const float* prot_out  = (const float*)d_in[10];
    float*       out       = (float*)d_out;

    cudaFuncSetAttribute(mega, cudaFuncAttributeMaxDynamicSharedMemorySize, 65536);
    mega<<<NBLK, 256, 65536>>>(prot_node, sub_node, int_index, Wp, bp, Ws, bs, wa,
                               sub_out, prot_out, out);
}

// round 14
// speedup vs baseline: 1.0052x; 1.0029x over previous
#include <cuda_runtime.h>
#include <float.h>
#include <math.h>

#define N_PROT 50000
#define N_SUB  2000
#define D      256     // D_PROT == D_SUB
#define DP     128     // D_PROJ
#define KERN   16
#define N_INT  64
#define NW     (N_PROT - KERN + 1)   // 49985

#define NBLK    444       // 3 * 148 SMs (launch_bounds(256,3)); single wave
#define RPB     113       // owned rows/windows per block: 444*113 = 50172 >= NW
#define GROWS   128       // RPB + 15 halo rows of g/s per block
#define N_RPART 8

// -------- device scratch (no allocations allowed) --------
__device__ float d_g[N_PROT + 32];   // +pad: halo dup writes near end
__device__ float d_s[N_PROT + 32];
__device__ float d_react_part[N_RPART * DP];
__device__ float d_blkVal[NBLK];
__device__ int   d_blkIdx[NBLK];
__device__ int   d_count;            // finalize ticket; reset by finalize

__device__ __forceinline__ float dot4(float4 a, float4 b) {
    return a.x*b.x + a.y*b.y + a.z*b.z + a.w*b.w;
}

// reduce 4 warp-accumulators; returns full sums at lanes 0(x0),8(x1),16(x2),24(x3)
__device__ __forceinline__ float reduce2(float x0, float x1, float x2, float x3, int lane) {
    #pragma unroll
    for (int o = 16; o >= 8; o >>= 1) {
        x0 += __shfl_xor_sync(0xffffffffu, x0, o);
        x1 += __shfl_xor_sync(0xffffffffu, x1, o);
        x2 += __shfl_xor_sync(0xffffffffu, x2, o);
        x3 += __shfl_xor_sync(0xffffffffu, x3, o);
    }
    float v = (lane < 8) ? x0 : (lane < 16) ? x1 : (lane < 24) ? x2 : x3;
    v += __shfl_xor_sync(0xffffffffu, v, 4);
    v += __shfl_xor_sync(0xffffffffu, v, 2);
    v += __shfl_xor_sync(0xffffffffu, v, 1);
    return v;
}

__global__ void __launch_bounds__(256, 3)
mega(const float* __restrict__ prot,
     const float* __restrict__ subn,
     const int*   __restrict__ idx,
     const float* __restrict__ Wp,
     const float* __restrict__ bp,
     const float* __restrict__ Ws,
     const float* __restrict__ bs,
     const float* __restrict__ wa,
     const float* __restrict__ sub_out,
     const float* __restrict__ prot_out,
     float* __restrict__ out)
{
    __shared__ float sv[D];           // v = Wp @ w1
    __shared__ float su[D];           // u = Wp @ ones
    __shared__ float sg[GROWS];
    __shared__ float ss[GROWS];
    __shared__ float sacc[8][32];
    __shared__ float ssumL[32];
    __shared__ float bval[256];
    __shared__ int   bidx[256];
    __shared__ int   s_last, s_top;
    __shared__ float attn[KERN];
    __shared__ float wrow[D];
    __shared__ float ts[DP];
    __shared__ float tpart[DP];
    __shared__ float dprot[D];
    __shared__ float dsub[D];

    int b    = blockIdx.x;
    int t    = threadIdx.x;
    int warp = t >> 5;
    int lane = t & 31;

    // ---------------- per-block v/u: warp w handles Wp rows [w*32, w*32+32) ----------------
    {
        float4 swa = ((const float4*)wa)[lane];   // wa[0:128] as float4 per lane
        #pragma unroll
        for (int bb = 0; bb < 8; bb++) {
            int j0 = warp * 32 + bb * 4;
            float4 w0 = ((const float4*)(Wp + (size_t)(j0 + 0) * DP))[lane];
            float4 w1 = ((const float4*)(Wp + (size_t)(j0 + 1) * DP))[lane];
            float4 w2 = ((const float4*)(Wp + (size_t)(j0 + 2) * DP))[lane];
            float4 w3 = ((const float4*)(Wp + (size_t)(j0 + 3) * DP))[lane];
            float r0 = reduce2(dot4(w0, swa), w0.x + w0.y + w0.z + w0.w,
                               dot4(w1, swa), w1.x + w1.y + w1.z + w1.w, lane);
            if (lane == 0)       sv[j0]     = r0;
            else if (lane == 8)  su[j0]     = r0;
            else if (lane == 16) sv[j0 + 1] = r0;
            else if (lane == 24) su[j0 + 1] = r0;
            float r1 = reduce2(dot4(w2, swa), w2.x + w2.y + w2.z + w2.w,
                               dot4(w3, swa), w3.x + w3.y + w3.z + w3.w, lane);
            if (lane == 0)       sv[j0 + 2] = r1;
            else if (lane == 8)  su[j0 + 2] = r1;
            else if (lane == 16) sv[j0 + 3] = r1;
            else if (lane == 24) su[j0 + 3] = r1;
        }
    }

    // ---------------- side roles (no ordering constraints until ticket) ----------------
    if (b == 0) {
        if (t < N_INT)
            out[(size_t)(N_PROT + N_SUB) * D + t] = (float)idx[t];
    } else if (b >= 16 && b < 16 + N_RPART) {
        // reaction partial over j-slice [j0, j0+32)
        int r  = b - 16;
        int j0 = r * 32;
        int col  = t & 31;
        int row8 = t >> 5;
        float acc = 0.f;
        #pragma unroll
        for (int p = 0; p < 8; p++)
            acc += subn[(size_t)idx[p * 8 + row8] * D + j0 + col];
        sacc[row8][col] = acc;
        __syncthreads();
        if (t < 32) {
            float s = 0.f;
            #pragma unroll
            for (int r8 = 0; r8 < 8; r8++) s += sacc[r8][t];
            ssumL[t] = s;
        }
        __syncthreads();
        if (t < DP) {
            float p = 0.f;
            #pragma unroll
            for (int j = 0; j < 32; j++)
                p += ssumL[j] * Ws[(j0 + j) * DP + t];
            d_react_part[r * DP + t] = p;
        }
    }
    // sub copy: blocks 0..399, 5 rows each (warps 0..4)
    if (b < 400 && warp < 5) {
        int row = b * 5 + warp;
        const float4* src = (const float4*)(subn + (size_t)row * D);
        float4*       dst = (float4*)(out + (size_t)(N_PROT + row) * D);
        dst[lane]      = src[lane];
        dst[lane + 32] = src[lane + 32];
    }

    __syncthreads();   // sv/su ready

    // ---------------- main tile: g/s (+halo) + copy, depth-2 pipelined ----------------
    {
        const float4* sv4 = (const float4*)sv;
        const float4* su4 = (const float4*)su;
        float4 va = sv4[lane], vc = sv4[lane + 32];
        float4 ua = su4[lane], uc = su4[lane + 32];

        int rb = b * RPB;                 // base global row of this tile
        int l0 = warp * 16;               // warp's local row range [l0, l0+16)

        // prefetch batch 0
        int gr0 = rb + l0;
        int gr1 = gr0 + 1;
        const float4* p0 = (const float4*)(prot + (size_t)(gr0 < N_PROT ? gr0 : 0) * D);
        const float4* p1 = (const float4*)(prot + (size_t)(gr1 < N_PROT ? gr1 : 0) * D);
        float4 a0 = p0[lane], c0 = p0[lane + 32];
        float4 a1 = p1[lane], c1 = p1[lane + 32];

        #pragma unroll
        for (int bi = 0; bi < 8; bi++) {
            int l   = l0 + bi * 2;
            int g0r = rb + l;
            int g1r = g0r + 1;

            float4 n0, n1, n2, n3;
            if (bi < 7) {
                int h0 = g0r + 2, h1 = g0r + 3;
                const float4* q0 = (const float4*)(prot + (size_t)(h0 < N_PROT ? h0 : 0) * D);
                const float4* q1 = (const float4*)(prot + (size_t)(h1 < N_PROT ? h1 : 0) * D);
                n0 = q0[lane]; n1 = q0[lane + 32];
                n2 = q1[lane]; n3 = q1[lane + 32];
            }

            bool ok0 = g0r < N_PROT;
            bool ok1 = g1r < N_PROT;

            // copy owned rows
            if (l < RPB && ok0) {
                float4* dst = (float4*)(out + (size_t)g0r * D);
                dst[lane]      = a0;
                dst[lane + 32] = c0;
            }
            if (l + 1 < RPB && ok1) {
                float4* dst = (float4*)(out + (size_t)g1r * D);
                dst[lane]      = a1;
                dst[lane + 32] = c1;
            }

            float r = reduce2(dot4(a0, va) + dot4(c0, vc),
                              dot4(a0, ua) + dot4(c0, uc),
                              dot4(a1, va) + dot4(c1, vc),
                              dot4(a1, ua) + dot4(c1, uc), lane);
            if (lane == 0) {
                sg[l] = ok0 ? r : -FLT_MAX;
                if (ok0) d_g[g0r] = r;
            } else if (lane == 8) {
                ss[l] = ok0 ? r : 0.f;
                if (ok0) d_s[g0r] = r;
            } else if (lane == 16) {
                sg[l + 1] = ok1 ? r : -FLT_MAX;
                if (ok1) d_g[g1r] = r;
            } else if (lane == 24) {
                ss[l + 1] = ok1 ? r : 0.f;
                if (ok1) d_s[g1r] = r;
            }

            a0 = n0; c0 = n1; a1 = n2; c1 = n3;
        }
    }
    __syncthreads();   // sg/ss complete

    // ---------------- windows (local, no barrier) ----------------
    {
        int   w = b * RPB + t;
        float A = -FLT_MAX;
        if (t < RPB && w < NW) {
            float m = sg[t];
            #pragma unroll
            for (int k = 1; k < KERN; k++) m = fmaxf(m, sg[t + k]);
            float wsum = 0.f, asum = 0.f;
            #pragma unroll
            for (int k = 0; k < KERN; k++) {
                float e = expf(sg[t + k] - m);
                wsum += e;
                asum += e * ss[t + k];
            }
            A = asum / wsum;
        }
        bval[t] = A;
        bidx[t] = (t < RPB && w < NW) ? w : 0x7fffffff;
        __syncthreads();

        for (int off = 128; off > 0; off >>= 1) {
            if (t < off) {
                float ov = bval[t + off];
                int   oi = bidx[t + off];
                if (ov > bval[t] || (ov == bval[t] && oi < bidx[t])) {
                    bval[t] = ov;
                    bidx[t] = oi;
                }
            }
            __syncthreads();
        }
        if (t == 0) {
            d_blkVal[b] = bval[0];
            d_blkIdx[b] = bidx[0];
        }
    }

    // ---------------- ticket: last block finalizes ----------------
    __syncthreads();
    if (t == 0) {
        __threadfence();
        s_last = (atomicAdd(&d_count, 1) == NBLK - 1);
    }
    __syncthreads();
    if (!s_last) return;

    // reduce 444 candidates -> top
    {
        float v1 = -FLT_MAX; int i1 = 0x7fffffff;
        if (t < NBLK)       { v1 = d_blkVal[t]; i1 = d_blkIdx[t]; }
        int t2 = t + 256;
        if (t2 < NBLK) {
            float v2 = d_blkVal[t2]; int i2 = d_blkIdx[t2];
            if (v2 > v1 || (v2 == v1 && i2 < i1)) { v1 = v2; i1 = i2; }
        }
        bval[t] = v1; bidx[t] = i1;
    }
    __syncthreads();
    for (int off = 128; off > 0; off >>= 1) {
        if (t < off) {
            float ov = bval[t + off];
            int   oi = bidx[t + off];
            if (ov > bval[t] || (ov == bval[t] && oi < bidx[t])) {
                bval[t] = ov;
                bidx[t] = oi;
            }
        }
        __syncthreads();
    }
    if (t == 0) { s_top = bidx[0]; d_count = 0; }   // reset for graph replay
    __syncthreads();
    int top = s_top;

    // attn (one warp)
    if (t < 32) {
        float gk = (t < KERN) ? d_g[top + t] : -FLT_MAX;
        float m = gk;
        #pragma unroll
        for (int o = 16; o > 0; o >>= 1)
            m = fmaxf(m, __shfl_xor_sync(0xffffffffu, m, o));
        float e = (t < KERN) ? expf(gk - m) : 0.f;
        float sum = e;
        #pragma unroll
        for (int o = 16; o > 0; o >>= 1)
            sum += __shfl_xor_sync(0xffffffffu, sum, o);
        if (t < KERN) attn[t] = e / sum;
    }
    __syncthreads();

    // weighted prot row
    {
        float acc = 0.f;
        #pragma unroll
        for (int k = 0; k < KERN; k++)
            acc += attn[k] * prot[(size_t)(top + k) * D + t];
        wrow[t] = acc;
    }
    __syncthreads();

    // top_score[d] = sum_r react_part[r][d] + 64*bs[d] + bp[d] + wrow @ Wp[:,d]
    {
        int c    = t & (DP - 1);
        int half = t >> 7;
        int j0   = half * (D / 2);
        float acc = 0.f;
        #pragma unroll 32
        for (int j = 0; j < D / 2; j++)
            acc += wrow[j0 + j] * Wp[(j0 + j) * DP + c];
        if (half) tpart[c] = acc;
        __syncthreads();
        if (!half) {
            float rp = 0.f;
            #pragma unroll
            for (int r = 0; r < N_RPART; r++) rp += d_react_part[r * DP + c];
            ts[c] = acc + tpart[c] + rp + (float)N_INT * bs[c] + bp[c];
        }
    }
    __syncthreads();

    // deltas
    {
        float dp_ = 0.f, ds_ = 0.f;
        #pragma unroll 32
        for (int d = 0; d < DP; d++) {
            float s = ts[d];
            dp_ += s * prot_out[d * D + t];
            ds_ += s * sub_out[d * D + t];
        }
        dprot[t] = dp_;
        dsub[t]  = ds_;
    }
    __syncthreads();

    // patch 16 prot rows (copies complete: every block ticketed after its stores)
    #pragma unroll
    for (int k = 0; k < KERN; k++)
        out[(size_t)(top + k) * D + t] += dprot[t];

    // patch 64 sub rows (set semantics; duplicates identical)
    #pragma unroll 4
    for (int m = 0; m < N_INT; m++) {
        int r = idx[m];
        out[(size_t)(N_PROT + r) * D + t] = subn[(size_t)r * D + t] + dsub[t];
    }
}

// ============================================================
extern "C" void kernel_launch(void* const* d_in, const int* in_sizes, int n_in,
                              void* d_out, int out_size)
{
    const float* prot_node = (const float*)d_in[0];
    const float* sub_node  = (const float*)d_in[1];
    const int*   int_index = (const int*)  d_in[2];
    const float* Wp        = (const float*)d_in[3];
    const float* bp        = (const float*)d_in[4];
    const float* Ws        = (const float*)d_in[5];
    const float* bs        = (const float*)d_in[6];
    const float* wa        = (const float*)d_in[7];
    const float* sub_out   = (const float*)d_in[9];
    const float* prot_out  = (const float*)d_in[10];
    float*       out       = (float*)d_out;

    mega<<<NBLK, 256>>>(prot_node, sub_node, int_index, Wp, bp, Ws, bs, wa,
                        sub_out, prot_out, out);
}

// round 15
// speedup vs baseline: 1.4898x; 1.4821x over previous
#include <cuda_runtime.h>
#include <float.h>
#include <math.h>
#include <stdint.h>

#define N_PROT 50000
#define N_SUB  2000
#define D      256     // D_PROT == D_SUB
#define DP     128     // D_PROJ
#define KERN   16
#define N_INT  64
#define NW     (N_PROT - KERN + 1)   // 49985

#define NBLK    444       // 3 * 148 SMs — all resident (launch_bounds(256,3))
#define PCHUNK  3125      // prot chunks of 16 rows
#define SCHUNK  125       // sub  chunks of 16 rows
#define TCHUNK  (PCHUNK + SCHUNK + 1)
#define NB_WIN  196       // 196*256 = 50176 >= NW
#define N_RPART 8

// -------- device scratch (no allocations allowed) --------
__device__ float d_gs[2 * (N_PROT + 32)];   // interleaved (g,s) pairs
__device__ float d_v[D];          // Wp @ w1
__device__ float d_u[D];          // Wp @ ones
__device__ float d_react_part[N_RPART * DP];
__device__ float d_blkVal[NB_WIN];
__device__ int   d_blkIdx[NB_WIN];
__device__ int   d_count;         // finalize ticket; reset by finalize
__device__ int   d_vu_done;       // v/u flag;        reset by finalize
__device__ int   d_bar;           // barrier;         reset by finalize

__device__ __forceinline__ float dot4(float4 a, float4 b) {
    return a.x*b.x + a.y*b.y + a.z*b.z + a.w*b.w;
}

// L2-policy-hinted 16B load (keep prot resident in L2 across graph replays)
__device__ __forceinline__ float4 ld4_keep(const float4* p, uint64_t pol) {
    float4 r;
    asm("ld.global.L2::cache_hint.v4.f32 {%0,%1,%2,%3}, [%4], %5;"
        : "=f"(r.x), "=f"(r.y), "=f"(r.z), "=f"(r.w)
        : "l"(p), "l"(pol));
    return r;
}
// L2-policy-hinted 16B store (out stream shouldn't displace prot)
__device__ __forceinline__ void st4_stream(float4* p, float4 v, uint64_t pol) {
    asm volatile("st.global.L2::cache_hint.v4.f32 [%0], {%1,%2,%3,%4}, %5;"
        :: "l"(p), "f"(v.x), "f"(v.y), "f"(v.z), "f"(v.w), "l"(pol) : "memory");
}

__global__ void __launch_bounds__(256, 3)
mega(const float* __restrict__ prot,
     const float* __restrict__ subn,
     const int*   __restrict__ idx,
     const float* __restrict__ Wp,
     const float* __restrict__ bp,
     const float* __restrict__ Ws,
     const float* __restrict__ bs,
     const float* __restrict__ wa,
     const float* __restrict__ sub_out,
     const float* __restrict__ prot_out,
     float* __restrict__ out)
{
    __shared__ float sv[D];           // staged v
    __shared__ float su[D];           // staged u
    __shared__ float sacc[8][32];
    __shared__ float ssumL[32];
    __shared__ float2 sgs[256 + KERN];   // (g,s) pairs for window tile
    __shared__ float bval[256];
    __shared__ int   bidx[256];
    __shared__ int   s_last, s_top;
    __shared__ float attn[KERN];
    __shared__ float wrow[D];
    __shared__ float ts[DP];
    __shared__ float tpart[DP];
    __shared__ float dprot[D];
    __shared__ float dsub[D];

    int b    = blockIdx.x;
    int t    = threadIdx.x;
    int warp = t >> 5;
    int lane = t & 31;

    uint64_t polKeep, polStream;
    asm("createpolicy.fractional.L2::evict_last.b64 %0, 1.0;"  : "=l"(polKeep));
    asm("createpolicy.fractional.L2::evict_first.b64 %0, 1.0;" : "=l"(polStream));

    // ---------------- producer prologue ----------------
    if (b < 32) {
        // v/u: one warp per Wp row, single coalesced float4 load
        int row = b * 8 + warp;
        float4 w = ((const float4*)(Wp + (size_t)row * DP))[lane];
        float4 a = ((const float4*)wa)[lane];
        float vv = dot4(w, a);
        float uu = w.x + w.y + w.z + w.w;
        #pragma unroll
        for (int o = 16; o > 0; o >>= 1) {
            vv += __shfl_xor_sync(0xffffffffu, vv, o);
            uu += __shfl_xor_sync(0xffffffffu, uu, o);
        }
        if (lane == 0) { d_v[row] = vv; d_u[row] = uu; }
        __syncthreads();
        if (t == 0) { __threadfence(); atomicAdd(&d_vu_done, 1); }
    } else if (b < 32 + N_RPART) {
        // reaction partial over j-slice [j0, j0+32)
        int r  = b - 32;
        int j0 = r * 32;
        int col  = t & 31;
        int row8 = t >> 5;
        float acc = 0.f;
        #pragma unroll
        for (int p = 0; p < 8; p++)
            acc += subn[(size_t)idx[p * 8 + row8] * D + j0 + col];
        sacc[row8][col] = acc;
        __syncthreads();
        if (t < 32) {
            float s = 0.f;
            #pragma unroll
            for (int r8 = 0; r8 < 8; r8++) s += sacc[r8][t];
            ssumL[t] = s;
        }
        __syncthreads();
        if (t < DP) {
            float p = 0.f;
            #pragma unroll
            for (int j = 0; j < 32; j++)
                p += ssumL[j] * Ws[(j0 + j) * DP + t];
            d_react_part[r * DP + t] = p;
        }
    }

    // ---------------- stage v/u to shared (all blocks) ----------------
    if (t == 0)
        while (((volatile int*)&d_vu_done)[0] < 32) __nanosleep(32);
    __syncthreads();
    sv[t] = d_v[t];
    su[t] = d_u[t];
    __syncthreads();

    // ---------------- phase A: prot copy + g/s matvec (pipelined, L2-hinted) ----------------
    {
        int chunk = b;
        if (chunk < PCHUNK) {
            const float4* sv4 = (const float4*)sv;
            const float4* su4 = (const float4*)su;
            float4 va = sv4[lane], vc = sv4[lane + 32];
            float4 ua = su4[lane], uc = su4[lane + 32];

            const float4* src = (const float4*)(prot + (size_t)(chunk * 16 + warp * 2) * D);
            float4 a0 = ld4_keep(src + lane,           polKeep);
            float4 c0 = ld4_keep(src + lane + 32,      polKeep);
            float4 a1 = ld4_keep(src + 64 + lane,      polKeep);
            float4 c1 = ld4_keep(src + 64 + lane + 32, polKeep);

            while (true) {
                int nxt = chunk + NBLK;
                bool hn = nxt < PCHUNK;
                float4 n0, n1, n2, n3;
                if (hn) {
                    const float4* nsrc = (const float4*)(prot + (size_t)(nxt * 16 + warp * 2) * D);
                    n0 = ld4_keep(nsrc + lane,           polKeep);
                    n1 = ld4_keep(nsrc + lane + 32,      polKeep);
                    n2 = ld4_keep(nsrc + 64 + lane,      polKeep);
                    n3 = ld4_keep(nsrc + 64 + lane + 32, polKeep);
                }

                int row = chunk * 16 + warp * 2;
                float4* dst = (float4*)(out + (size_t)row * D);
                st4_stream(dst + lane,           a0, polStream);
                st4_stream(dst + lane + 32,      c0, polStream);
                st4_stream(dst + 64 + lane,      a1, polStream);
                st4_stream(dst + 64 + lane + 32, c1, polStream);

                // reduce: 4 accumulators -> full sums at lanes 0,8,16,24
                float g0 = dot4(a0, va) + dot4(c0, vc);
                float s0 = dot4(a0, ua) + dot4(c0, uc);
                float g1 = dot4(a1, va) + dot4(c1, vc);
                float s1 = dot4(a1, ua) + dot4(c1, uc);
                #pragma unroll
                for (int o = 16; o >= 8; o >>= 1) {
                    g0 += __shfl_xor_sync(0xffffffffu, g0, o);
                    s0 += __shfl_xor_sync(0xffffffffu, s0, o);
                    g1 += __shfl_xor_sync(0xffffffffu, g1, o);
                    s1 += __shfl_xor_sync(0xffffffffu, s1, o);
                }
                float v = (lane < 8) ? g0 : (lane < 16) ? s0 : (lane < 24) ? g1 : s1;
                v += __shfl_xor_sync(0xffffffffu, v, 4);
                v += __shfl_xor_sync(0xffffffffu, v, 2);
                v += __shfl_xor_sync(0xffffffffu, v, 1);

                // gather to lane 0 and store one float4 = (g0,s0,g1,s1)
                float pg0 = __shfl_sync(0xffffffffu, v, 0);
                float ps0 = __shfl_sync(0xffffffffu, v, 8);
                float pg1 = __shfl_sync(0xffffffffu, v, 16);
                float ps1 = __shfl_sync(0xffffffffu, v, 24);
                if (lane == 0)
                    *(float4*)&d_gs[2 * row] = make_float4(pg0, ps0, pg1, ps1);

                if (!hn) break;
                a0 = n0; c0 = n1; a1 = n2; c1 = n3;
                chunk = nxt;
            }
        }
    }

    // ---------------- phase A': sub copy + idx tail ----------------
    for (int chunk = b; chunk < TCHUNK; chunk += NBLK) {
        if (chunk >= PCHUNK && chunk < PCHUNK + SCHUNK) {
            int row = (chunk - PCHUNK) * 16 + warp * 2;
            const float4* src = (const float4*)(subn + (size_t)row * D);
            float4*       dst = (float4*)(out + (size_t)(N_PROT + row) * D);
            st4_stream(dst + lane,           src[lane],           polStream);
            st4_stream(dst + lane + 32,      src[lane + 32],      polStream);
            st4_stream(dst + 64 + lane,      src[64 + lane],      polStream);
            st4_stream(dst + 64 + lane + 32, src[64 + lane + 32], polStream);
        } else if (chunk == PCHUNK + SCHUNK) {
            if (t < N_INT)
                out[(size_t)(N_PROT + N_SUB) * D + t] = (float)idx[t];
        }
    }

    // ---------------- grid barrier (arrive; non-phase-B exit) ----------------
    __syncthreads();
    if (t == 0) {
        __threadfence();
        atomicAdd(&d_bar, 1);
    }
    if (b >= NB_WIN) return;
    if (t == 0) {
        while (((volatile int*)&d_bar)[0] < NBLK) __nanosleep(64);
        __threadfence();
    }
    __syncthreads();

    // ---------------- phase B: windows + block argmax ----------------
    {
        int base = b * 256;
        const float2* gs2 = (const float2*)d_gs;
        for (int i = t; i < 256 + KERN - 1; i += 256) {
            int gi = base + i;
            sgs[i] = (gi < N_PROT) ? gs2[gi] : make_float2(-FLT_MAX, 0.f);
        }
        __syncthreads();

        int   w = base + t;
        float A = -FLT_MAX;
        if (w < NW) {
            float m = sgs[t].x;
            #pragma unroll
            for (int k = 1; k < KERN; k++) m = fmaxf(m, sgs[t + k].x);
            float wsum = 0.f, asum = 0.f;
            #pragma unroll
            for (int k = 0; k < KERN; k++) {
                float e = expf(sgs[t + k].x - m);
                wsum += e;
                asum += e * sgs[t + k].y;
            }
            A = asum / wsum;
        }
        bval[t] = A;
        bidx[t] = w;
        __syncthreads();

        for (int off = 128; off > 0; off >>= 1) {
            if (t < off) {
                float ov = bval[t + off];
                int   oi = bidx[t + off];
                if (ov > bval[t] || (ov == bval[t] && oi < bidx[t])) {
                    bval[t] = ov;
                    bidx[t] = oi;
                }
            }
            __syncthreads();
        }
        if (t == 0) {
            d_blkVal[b] = bval[0];
            d_blkIdx[b] = bidx[0];
        }
    }

    // ---------------- ticket among window blocks: last finalizes ----------------
    __syncthreads();
    if (t == 0) {
        __threadfence();
        s_last = (atomicAdd(&d_count, 1) == NB_WIN - 1);
    }
    __syncthreads();
    if (!s_last) return;

    // reduce 196 candidates -> top
    if (t < NB_WIN) { bval[t] = d_blkVal[t]; bidx[t] = d_blkIdx[t]; }
    else            { bval[t] = -FLT_MAX;    bidx[t] = 0x7fffffff; }
    __syncthreads();
    for (int off = 128; off > 0; off >>= 1) {
        if (t < off) {
            float ov = bval[t + off];
            int   oi = bidx[t + off];
            if (ov > bval[t] || (ov == bval[t] && oi < bidx[t])) {
                bval[t] = ov;
                bidx[t] = oi;
            }
        }
        __syncthreads();
    }
    if (t == 0) {
        s_top = bidx[0];
        d_count = 0; d_vu_done = 0; d_bar = 0;   // reset for graph replay
    }
    __syncthreads();
    int top = s_top;

    // attn (one warp)
    if (t < 32) {
        float gk = (t < KERN) ? d_gs[2 * (top + t)] : -FLT_MAX;
        float m = gk;
        #pragma unroll
        for (int o = 16; o > 0; o >>= 1)
            m = fmaxf(m, __shfl_xor_sync(0xffffffffu, m, o));
        float e = (t < KERN) ? expf(gk - m) : 0.f;
        float sum = e;
        #pragma unroll
        for (int o = 16; o > 0; o >>= 1)
            sum += __shfl_xor_sync(0xffffffffu, sum, o);
        if (t < KERN) attn[t] = e / sum;
    }
    __syncthreads();

    // weighted prot row
    {
        float acc = 0.f;
        #pragma unroll
        for (int k = 0; k < KERN; k++)
            acc += attn[k] * prot[(size_t)(top + k) * D + t];
        wrow[t] = acc;
    }
    __syncthreads();

    // top_score[d] = sum_r react_part[r][d] + 64*bs[d] + bp[d] + wrow @ Wp[:,d]
    {
        int c    = t & (DP - 1);
        int half = t >> 7;
        int j0   = half * (D / 2);
        float acc = 0.f;
        #pragma unroll 32
        for (int j = 0; j < D / 2; j++)
            acc += wrow[j0 + j] * Wp[(j0 + j) * DP + c];
        if (half) tpart[c] = acc;
        __syncthreads();
        if (!half) {
            float rp = 0.f;
            #pragma unroll
            for (int r = 0; r < N_RPART; r++) rp += d_react_part[r * DP + c];
            ts[c] = acc + tpart[c] + rp + (float)N_INT * bs[c] + bp[c];
        }
    }
    __syncthreads();

    // deltas
    {
        float dp_ = 0.f, ds_ = 0.f;
        #pragma unroll 32
        for (int d = 0; d < DP; d++) {
            float s = ts[d];
            dp_ += s * prot_out[d * D + t];
            ds_ += s * sub_out[d * D + t];
        }
        dprot[t] = dp_;
        dsub[t]  = ds_;
    }
    __syncthreads();

    // patch 16 prot rows
    #pragma unroll
    for (int k = 0; k < KERN; k++)
        out[(size_t)(top + k) * D + t] += dprot[t];

    // patch 64 sub rows (set semantics; duplicates identical)
    #pragma unroll 4
    for (int m = 0; m < N_INT; m++) {
        int r = idx[m];
        out[(size_t)(N_PROT + r) * D + t] = subn[(size_t)r * D + t] + dsub[t];
    }
}

// ============================================================
extern "C" void kernel_launch(void* const* d_in, const int* in_sizes, int n_in,
                              void* d_out, int out_size)
{
    const float* prot_node = (const float*)d_in[0];
    const float* sub_node  = (const float*)d_in[1];
    const int*   int_index = (const int*)  d_in[2];
    const float* Wp        = (const float*)d_in[3];
    const float* bp        = (const float*)d_in[4];
    const float* Ws        = (const float*)d_in[5];
    const float* bs        = (const float*)d_in[6];
    const float* wa        = (const float*)d_in[7];
    const float* sub_out   = (const float*)d_in[9];
    const float* prot_out  = (const float*)d_in[10];
    float*       out       = (float*)d_out;

    mega<<<NBLK, 256>>>(prot_node, sub_node, int_index, Wp, bp, Ws, bs, wa,
                        sub_out, prot_out, out);
}

// round 17
// speedup vs baseline: 1.5013x; 1.0077x over previous
#include <cuda_runtime.h>
#include <float.h>
#include <math.h>
#include <stdint.h>

#define N_PROT 50000
#define N_SUB  2000
#define D      256     // D_PROT == D_SUB
#define DP     128     // D_PROJ
#define KERN   16
#define N_INT  64
#define NW     (N_PROT - KERN + 1)   // 49985

#define NBLK    592       // 4 * 148 SMs — all resident (launch_bounds(256,4))
#define PCHUNK  3125      // prot chunks of 16 rows
#define SCHUNK  125       // sub  chunks of 16 rows
#define TCHUNK  (PCHUNK + SCHUNK + 1)
#define NB_WIN  196       // 196*256 = 50176 >= NW
#define N_RPART 8

// -------- device scratch (no allocations allowed) --------
__device__ float d_gs[2 * (N_PROT + 32)];   // interleaved (g,s) pairs
__device__ float d_v[D];          // Wp @ w1
__device__ float d_u[D];          // Wp @ ones
__device__ float d_react_part[N_RPART * DP];
__device__ float d_blkVal[NB_WIN];
__device__ int   d_blkIdx[NB_WIN];
__device__ int   d_count;         // finalize ticket; reset by finalize
__device__ int   d_vu_done;       // v/u flag;        reset by finalize
__device__ int   d_bar;           // barrier;         reset by finalize

__device__ __forceinline__ float dot4(float4 a, float4 b) {
    return a.x*b.x + a.y*b.y + a.z*b.z + a.w*b.w;
}

// L2-policy-hinted 16B load (keep prot resident in L2 across graph replays)
__device__ __forceinline__ float4 ld4_keep(const float4* p, uint64_t pol) {
    float4 r;
    asm("ld.global.L2::cache_hint.v4.f32 {%0,%1,%2,%3}, [%4], %5;"
        : "=f"(r.x), "=f"(r.y), "=f"(r.z), "=f"(r.w)
        : "l"(p), "l"(pol));
    return r;
}
// L2-policy-hinted 16B store (out stream shouldn't displace prot)
__device__ __forceinline__ void st4_stream(float4* p, float4 v, uint64_t pol) {
    asm volatile("st.global.L2::cache_hint.v4.f32 [%0], {%1,%2,%3,%4}, %5;"
        :: "l"(p), "f"(v.x), "f"(v.y), "f"(v.z), "f"(v.w), "l"(pol) : "memory");
}

__global__ void __launch_bounds__(256, 4)
mega(const float* __restrict__ prot,
     const float* __restrict__ subn,
     const int*   __restrict__ idx,
     const float* __restrict__ Wp,
     const float* __restrict__ bp,
     const float* __restrict__ Ws,
     const float* __restrict__ bs,
     const float* __restrict__ wa,
     const float* __restrict__ sub_out,
     const float* __restrict__ prot_out,
     float* __restrict__ out)
{
    __shared__ float sv[D];           // staged v
    __shared__ float su[D];           // staged u
    __shared__ float sacc[8][32];
    __shared__ float ssumL[32];
    __shared__ float2 sgs[256 + KERN];   // (g,s) pairs for window tile
    __shared__ float bval[256];
    __shared__ int   bidx[256];
    __shared__ int   s_last, s_top;
    __shared__ float attn[KERN];
    __shared__ float wrow[D];
    __shared__ float ts[DP];
    __shared__ float tpart[DP];
    __shared__ float dprot[D];
    __shared__ float dsub[D];

    int b    = blockIdx.x;
    int t    = threadIdx.x;
    int warp = t >> 5;
    int lane = t & 31;

    uint64_t polKeep, polStream;
    asm("createpolicy.fractional.L2::evict_last.b64 %0, 1.0;"  : "=l"(polKeep));
    asm("createpolicy.fractional.L2::evict_first.b64 %0, 1.0;" : "=l"(polStream));

    // ---------------- producer prologue ----------------
    if (b < 32) {
        // v/u: one warp per Wp row, single coalesced float4 load
        int row = b * 8 + warp;
        float4 w = ((const float4*)(Wp + (size_t)row * DP))[lane];
        float4 a = ((const float4*)wa)[lane];
        float vv = dot4(w, a);
        float uu = w.x + w.y + w.z + w.w;
        #pragma unroll
        for (int o = 16; o > 0; o >>= 1) {
            vv += __shfl_xor_sync(0xffffffffu, vv, o);
            uu += __shfl_xor_sync(0xffffffffu, uu, o);
        }
        if (lane == 0) { d_v[row] = vv; d_u[row] = uu; }
        __syncthreads();
        if (t == 0) { __threadfence(); atomicAdd(&d_vu_done, 1); }
    } else if (b < 32 + N_RPART) {
        // reaction partial over j-slice [j0, j0+32)
        int r  = b - 32;
        int j0 = r * 32;
        int col  = t & 31;
        int row8 = t >> 5;
        float acc = 0.f;
        #pragma unroll
        for (int p = 0; p < 8; p++)
            acc += subn[(size_t)idx[p * 8 + row8] * D + j0 + col];
        sacc[row8][col] = acc;
        __syncthreads();
        if (t < 32) {
            float s = 0.f;
            #pragma unroll
            for (int r8 = 0; r8 < 8; r8++) s += sacc[r8][t];
            ssumL[t] = s;
        }
        __syncthreads();
        if (t < DP) {
            float p = 0.f;
            #pragma unroll
            for (int j = 0; j < 32; j++)
                p += ssumL[j] * Ws[(j0 + j) * DP + t];
            d_react_part[r * DP + t] = p;
        }
    }

    // ---------------- stage v/u to shared (all blocks) ----------------
    if (t == 0)
        while (((volatile int*)&d_vu_done)[0] < 32) __nanosleep(32);
    __syncthreads();
    sv[t] = d_v[t];
    su[t] = d_u[t];
    __syncthreads();

    // ---------------- phase A: prot copy + g/s matvec (pipelined, L2-hinted) ----------------
    {
        int chunk = b;
        if (chunk < PCHUNK) {
            const float4* sv4 = (const float4*)sv;
            const float4* su4 = (const float4*)su;

            const float4* src = (const float4*)(prot + (size_t)(chunk * 16 + warp * 2) * D);
            float4 a0 = ld4_keep(src + lane,           polKeep);
            float4 c0 = ld4_keep(src + lane + 32,      polKeep);
            float4 a1 = ld4_keep(src + 64 + lane,      polKeep);
            float4 c1 = ld4_keep(src + 64 + lane + 32, polKeep);

            while (true) {
                int nxt = chunk + NBLK;
                bool hn = nxt < PCHUNK;
                float4 n0, n1, n2, n3;
                if (hn) {
                    const float4* nsrc = (const float4*)(prot + (size_t)(nxt * 16 + warp * 2) * D);
                    n0 = ld4_keep(nsrc + lane,           polKeep);
                    n1 = ld4_keep(nsrc + lane + 32,      polKeep);
                    n2 = ld4_keep(nsrc + 64 + lane,      polKeep);
                    n3 = ld4_keep(nsrc + 64 + lane + 32, polKeep);
                }

                int row = chunk * 16 + warp * 2;
                float4* dst = (float4*)(out + (size_t)row * D);
                st4_stream(dst + lane,           a0, polStream);
                st4_stream(dst + lane + 32,      c0, polStream);
                st4_stream(dst + 64 + lane,      a1, polStream);
                st4_stream(dst + 64 + lane + 32, c1, polStream);

                // v/u read from shared in-loop (keeps register count <= 64)
                float4 va = sv4[lane], vc = sv4[lane + 32];
                float4 ua = su4[lane], uc = su4[lane + 32];

                float g0 = dot4(a0, va) + dot4(c0, vc);
                float s0 = dot4(a0, ua) + dot4(c0, uc);
                float g1 = dot4(a1, va) + dot4(c1, vc);
                float s1 = dot4(a1, ua) + dot4(c1, uc);
                #pragma unroll
                for (int o = 16; o >= 8; o >>= 1) {
                    g0 += __shfl_xor_sync(0xffffffffu, g0, o);
                    s0 += __shfl_xor_sync(0xffffffffu, s0, o);
                    g1 += __shfl_xor_sync(0xffffffffu, g1, o);
                    s1 += __shfl_xor_sync(0xffffffffu, s1, o);
                }
                float v = (lane < 8) ? g0 : (lane < 16) ? s0 : (lane < 24) ? g1 : s1;
                v += __shfl_xor_sync(0xffffffffu, v, 4);
                v += __shfl_xor_sync(0xffffffffu, v, 2);
                v += __shfl_xor_sync(0xffffffffu, v, 1);

                float pg0 = __shfl_sync(0xffffffffu, v, 0);
                float ps0 = __shfl_sync(0xffffffffu, v, 8);
                float pg1 = __shfl_sync(0xffffffffu, v, 16);
                float ps1 = __shfl_sync(0xffffffffu, v, 24);
                if (lane == 0)
                    *(float4*)&d_gs[2 * row] = make_float4(pg0, ps0, pg1, ps1);

                if (!hn) break;
                a0 = n0; c0 = n1; a1 = n2; c1 = n3;
                chunk = nxt;
            }
        }
    }

    // ---------------- phase A': sub copy + idx tail ----------------
    for (int chunk = b; chunk < TCHUNK; chunk += NBLK) {
        if (chunk >= PCHUNK && chunk < PCHUNK + SCHUNK) {
            int row = (chunk - PCHUNK) * 16 + warp * 2;
            const float4* src = (const float4*)(subn + (size_t)row * D);
            float4*       dst = (float4*)(out + (size_t)(N_PROT + row) * D);
            st4_stream(dst + lane,           src[lane],           polStream);
            st4_stream(dst + lane + 32,      src[lane + 32],      polStream);
            st4_stream(dst + 64 + lane,      src[64 + lane],      polStream);
            st4_stream(dst + 64 + lane + 32, src[64 + lane + 32], polStream);
        } else if (chunk == PCHUNK + SCHUNK) {
            if (t < N_INT)
                out[(size_t)(N_PROT + N_SUB) * D + t] = (float)idx[t];
        }
    }

    // ---------------- grid barrier (arrive; non-phase-B exit) ----------------
    __syncthreads();
    if (t == 0) {
        __threadfence();
        atomicAdd(&d_bar, 1);
    }
    if (b >= NB_WIN) return;
    if (t == 0) {
        while (((volatile int*)&d_bar)[0] < NBLK) __nanosleep(64);
        __threadfence();
    }
    __syncthreads();

    // ---------------- phase B: windows + block argmax ----------------
    {
        int base = b * 256;
        const float2* gs2 = (const float2*)d_gs;
        for (int i = t; i < 256 + KERN - 1; i += 256) {
            int gi = base + i;
            sgs[i] = (gi < N_PROT) ? gs2[gi] : make_float2(-FLT_MAX, 0.f);
        }
        __syncthreads();

        int   w = base + t;
        float A = -FLT_MAX;
        if (w < NW) {
            float m = sgs[t].x;
            #pragma unroll
            for (int k = 1; k < KERN; k++) m = fmaxf(m, sgs[t + k].x);
            float wsum = 0.f, asum = 0.f;
            #pragma unroll
            for (int k = 0; k < KERN; k++) {
                float e = expf(sgs[t + k].x - m);
                wsum += e;
                asum += e * sgs[t + k].y;
            }
            A = asum / wsum;
        }
        bval[t] = A;
        bidx[t] = w;
        __syncthreads();

        for (int off = 128; off > 0; off >>= 1) {
            if (t < off) {
                float ov = bval[t + off];
                int   oi = bidx[t + off];
                if (ov > bval[t] || (ov == bval[t] && oi < bidx[t])) {
                    bval[t] = ov;
                    bidx[t] = oi;
                }
            }
            __syncthreads();
        }
        if (t == 0) {
            d_blkVal[b] = bval[0];
            d_blkIdx[b] = bidx[0];
        }
    }

    // ---------------- ticket among window blocks: last finalizes ----------------
    __syncthreads();
    if (t == 0) {
        __threadfence();
        s_last = (atomicAdd(&d_count, 1) == NB_WIN - 1);
    }
    __syncthreads();
    if (!s_last) return;

    // reduce 196 candidates -> top
    if (t < NB_WIN) { bval[t] = d_blkVal[t]; bidx[t] = d_blkIdx[t]; }
    else            { bval[t] = -FLT_MAX;    bidx[t] = 0x7fffffff; }
    __syncthreads();
    for (int off = 128; off > 0; off >>= 1) {
        if (t < off) {
            float ov = bval[t + off];
            int   oi = bidx[t + off];
            if (ov > bval[t] || (ov == bval[t] && oi < bidx[t])) {
                bval[t] = ov;
                bidx[t] = oi;
            }
        }
        __syncthreads();
    }
    if (t == 0) {
        s_top = bidx[0];
        d_count = 0; d_vu_done = 0; d_bar = 0;   // reset for graph replay
    }
    __syncthreads();
    int top = s_top;

    // attn (one warp)
    if (t < 32) {
        float gk = (t < KERN) ? d_gs[2 * (top + t)] : -FLT_MAX;
        float m = gk;
        #pragma unroll
        for (int o = 16; o > 0; o >>= 1)
            m = fmaxf(m, __shfl_xor_sync(0xffffffffu, m, o));
        float e = (t < KERN) ? expf(gk - m) : 0.f;
        float sum = e;
        #pragma unroll
        for (int o = 16; o > 0; o >>= 1)
            sum += __shfl_xor_sync(0xffffffffu, sum, o);
        if (t < KERN) attn[t] = e / sum;
    }
    __syncthreads();

    // weighted prot row
    {
        float acc = 0.f;
        #pragma unroll
        for (int k = 0; k < KERN; k++)
            acc += attn[k] * prot[(size_t)(top + k) * D + t];
        wrow[t] = acc;
    }
    __syncthreads();

    // top_score[d] = sum_r react_part[r][d] + 64*bs[d] + bp[d] + wrow @ Wp[:,d]
    {
        int c    = t & (DP - 1);
        int half = t >> 7;
        int j0   = half * (D / 2);
        float acc = 0.f;
        #pragma unroll 32
        for (int j = 0; j < D / 2; j++)
            acc += wrow[j0 + j] * Wp[(j0 + j) * DP + c];
        if (half) tpart[c] = acc;
        __syncthreads();
        if (!half) {
            float rp = 0.f;
            #pragma unroll
            for (int r = 0; r < N_RPART; r++) rp += d_react_part[r * DP + c];
            ts[c] = acc + tpart[c] + rp + (float)N_INT * bs[c] + bp[c];
        }
    }
    __syncthreads();

    // deltas
    {
        float dp_ = 0.f, ds_ = 0.f;
        #pragma unroll 32
        for (int d = 0; d < DP; d++) {
            float s = ts[d];
            dp_ += s * prot_out[d * D + t];
            ds_ += s * sub_out[d * D + t];
        }
        dprot[t] = dp_;
        dsub[t]  = ds_;
    }
    __syncthreads();

    // patch 16 prot rows
    #pragma unroll
    for (int k = 0; k < KERN; k++)
        out[(size_t)(top + k) * D + t] += dprot[t];

    // patch 64 sub rows (set semantics; duplicates identical)
    #pragma unroll 4
    for (int m = 0; m < N_INT; m++) {
        int r = idx[m];
        out[(size_t)(N_PROT + r) * D + t] = subn[(size_t)r * D + t] + dsub[t];
    }
}

// ============================================================
extern "C" void kernel_launch(void* const* d_in, const int* in_sizes, int n_in,
                              void* d_out, int out_size)
{
    const float* prot_node = (const float*)d_in[0];
    const float* sub_node  = (const float*)d_in[1];
    const int*   int_index = (const int*)  d_in[2];
    const float* Wp        = (const float*)d_in[3];
    const float* bp        = (const float*)d_in[4];
    const float* Ws        = (const float*)d_in[5];
    const float* bs        = (const float*)d_in[6];
    const float* wa        = (const float*)d_in[7];
    const float* sub_out   = (const float*)d_in[9];
    const float* prot_out  = (const float*)d_in[10];
    float*       out       = (float*)d_out;

    mega<<<NBLK, 256>>>(prot_node, sub_node, int_index, Wp, bp, Ws, bs, wa,
                        sub_out, prot_out, out);
}